// round 16
// baseline (speedup 1.0000x reference)
#include <cuda_runtime.h>
#include <cuda_fp16.h>

#define S_TOT 4096
#define N_OBJ 32
#define H_D   64
#define PA    68                 // f32 row stride (floats); conflict-free LDS.128
#define AH    72                 // fp16 row stride (halves) = 144B; 16B chunks conflict-free
#define NPAIR 496
#define SAMP_F (N_OBJ * PA)      // 2176 floats per sample region
#define SAMP_H (N_OBJ * AH)      // 2304 halves per sample region

typedef unsigned long long u64;

__device__ __forceinline__ u64 pack2(float lo, float hi) {
    u64 r; asm("mov.b64 %0, {%1, %2};" : "=l"(r) : "f"(lo), "f"(hi)); return r;
}
__device__ __forceinline__ void unpack2(u64 v, float& lo, float& hi) {
    asm("mov.b64 {%0, %1}, %2;" : "=f"(lo), "=f"(hi) : "l"(v));
}
__device__ __forceinline__ u64 ffma2(u64 a, u64 b, u64 c) {
    u64 d; asm("fma.rn.f32x2 %0, %1, %2, %3;" : "=l"(d) : "l"(a), "l"(b), "l"(c)); return d;
}
__device__ __forceinline__ float tanh_fast(float x) {   // 1 MUFU
    float y; asm("tanh.approx.f32 %0, %1;" : "=f"(y) : "f"(x)); return y;
}
__device__ __forceinline__ __half2 mg_h2tanh(__half2 x) {  // 1 MUFU for 2 values
    unsigned xi = *(unsigned*)&x, yi;
    asm("tanh.approx.f16x2 %0, %1;" : "=r"(yi) : "r"(xi));
    return *(__half2*)&yi;
}
__device__ __forceinline__ unsigned h2u(__half2 h) { return *(unsigned*)&h; }
__device__ __forceinline__ int rb(int x) { return x * 31 - ((x * (x - 1)) >> 1); }

__global__ __launch_bounds__(256, 3)
void magnet_main(const float* __restrict__ X,     // [S,32,4]
                 const float* __restrict__ L1W,   // [64,4]
                 const float* __restrict__ L1b,   // [64]
                 const float* __restrict__ L2W,   // [64,64]
                 const float* __restrict__ L2b,   // [64]
                 const float* __restrict__ I1W,   // [64,64]
                 const float* __restrict__ I2W,   // [8,64]
                 const float* __restrict__ I3,    // [992,2,4]
                 const float* __restrict__ S1W,   // [4,4]
                 const float* __restrict__ S1b,   // [4]
                 const float* __restrict__ S2W,   // [32,2,2]
                 const float* __restrict__ S2b,   // [32,2]
                 float* __restrict__ out)         // [S,32,2]
{
    // 2 samples per block; encoder activations row-major f32 [s][obj][PA]
    __shared__ __align__(16) float bufT1[2 * SAMP_F];       // h1; reused as fp16 a [s][obj][AH]
    __shared__ __align__(16) float bufT2_sPair[2 * SAMP_F]; // h2; alias sPair [s][496][4]
    __shared__ __align__(16) float sW[H_D * H_D];           // L2W then I1W, row-major [c][k]
    __shared__ __align__(16) float sI2[H_D * 8];            // [h][f]
    __shared__ __align__(16) float sX[2 * N_OBJ * 4];
    __shared__ __align__(16) float sL1W[H_D * 4];
    __shared__ float sL1b[H_D];
    __shared__ float sL2b[H_D];
    __shared__ float sRes[2 * N_OBJ * 2];

    float* bufT2 = bufT2_sPair;
    float* sPair = bufT2_sPair;

    const int tid  = threadIdx.x;
    const int bid  = blockIdx.x;
    const int wS   = tid >> 5;       // warp 0..7
    const int lane = tid & 31;       // = object in encoder stages
    const int c0   = wS * 8;         // 8 channels per warp (warp-uniform)

    // ---- staging ----
    {
        const float4* W2 = (const float4*)L2W;
        #pragma unroll
        for (int q = 0; q < 4; q++)
            ((float4*)sW)[tid + q * 256] = __ldg(W2 + tid + q * 256);
        #pragma unroll
        for (int e = 0; e < 2; e++) {                 // sI2[h][f] = I2W[f][h]
            int idx = tid + e * 256;
            int h = idx >> 3, f = idx & 7;
            sI2[idx] = __ldg(I2W + f * 64 + h);
        }
        if (tid < 64)        ((float4*)sX)[tid]        = __ldg(((const float4*)X) + bid * 64 + tid);
        else if (tid < 128)  ((float4*)sL1W)[tid - 64] = __ldg(((const float4*)L1W) + (tid - 64));
        else if (tid < 192)  sL1b[tid - 128] = __ldg(L1b + tid - 128);
        else                 sL2b[tid - 192] = __ldg(L2b + tid - 192);
    }
    __syncthreads();

    // ---- stage 1: h1 = relu(x @ L1W^T + L1b), row-major float4 writes ----
    {
        float4 x0 = ((const float4*)sX)[lane];
        float4 x1 = ((const float4*)sX)[N_OBJ + lane];
        float4 oA0, oA1, oB0, oB1;
        float* pA0 = (float*)&oA0; float* pA1 = (float*)&oA1;
        float* pB0 = (float*)&oB0; float* pB1 = (float*)&oB1;
        #pragma unroll
        for (int q = 0; q < 8; q++) {
            int c = c0 + q;
            float4 w = ((const float4*)sL1W)[c];         // broadcast (both samples)
            float b = sL1b[c];
            float v0 = fmaf(x0.x, w.x, fmaf(x0.y, w.y, fmaf(x0.z, w.z, fmaf(x0.w, w.w, b))));
            float v1 = fmaf(x1.x, w.x, fmaf(x1.y, w.y, fmaf(x1.z, w.z, fmaf(x1.w, w.w, b))));
            if (q < 4) { pA0[q]   = fmaxf(v0, 0.f); pB0[q]   = fmaxf(v1, 0.f); }
            else       { pA1[q-4] = fmaxf(v0, 0.f); pB1[q-4] = fmaxf(v1, 0.f); }
        }
        *(float4*)&bufT1[lane * PA + c0]              = oA0;
        *(float4*)&bufT1[lane * PA + c0 + 4]          = oA1;
        *(float4*)&bufT1[SAMP_F + lane * PA + c0]     = oB0;
        *(float4*)&bufT1[SAMP_F + lane * PA + c0 + 4] = oB1;
    }
    // ---- self term (64 threads = 2 samples x 32 obj) -> sRes ----
    if (tid < 64) {
        int o = tid & 31;
        float4 xv = ((const float4*)sX)[tid];
        float hs[4];
        #pragma unroll
        for (int f = 0; f < 4; f++) {
            float4 w = __ldg(((const float4*)S1W) + f);
            hs[f] = fmaxf(xv.x*w.x + xv.y*w.y + xv.z*w.z + xv.w*w.w + __ldg(S1b + f), 0.f);
        }
        float4 s2 = __ldg(((const float4*)S2W) + o);
        sRes[tid * 2 + 0] = hs[0] * s2.x + hs[1] * s2.y + __ldg(S2b + o * 2 + 0);
        sRes[tid * 2 + 1] = hs[2] * s2.z + hs[3] * s2.w + __ldg(S2b + o * 2 + 1);
    }
    __syncthreads();

    // ---- stage 2: h2 = relu(h1 @ L2W^T + L2b) -> bufT2 row-major ----
    {
        u64 acc0[8], acc1[8];
        #pragma unroll
        for (int q = 0; q < 8; q++) { acc0[q] = pack2(sL2b[c0 + q], 0.f); acc1[q] = acc0[q]; }
        const float4* hvA = (const float4*)&bufT1[lane * PA];
        const float4* hvB = (const float4*)&bufT1[SAMP_F + lane * PA];
        #pragma unroll
        for (int k4 = 0; k4 < 16; k4++) {
            float4 hA = hvA[k4], hB = hvB[k4];           // conflict-free LDS.128
            u64 hA0 = pack2(hA.x, hA.y), hA1 = pack2(hA.z, hA.w);
            u64 hB0 = pack2(hB.x, hB.y), hB1 = pack2(hB.z, hB.w);
            int kb = k4 * 4;
            #pragma unroll
            for (int q = 0; q < 8; q++) {
                ulonglong2 w = *(const ulonglong2*)&sW[(c0 + q) * 64 + kb];  // bcast, 2 samples
                acc0[q] = ffma2(hA0, w.x, acc0[q]); acc0[q] = ffma2(hA1, w.y, acc0[q]);
                acc1[q] = ffma2(hB0, w.x, acc1[q]); acc1[q] = ffma2(hB1, w.y, acc1[q]);
            }
        }
        float4 o0, o1; float lo, hi;
        float* p0 = (float*)&o0; float* p1 = (float*)&o1;
        #pragma unroll
        for (int q = 0; q < 8; q++) {
            unpack2(acc0[q], lo, hi);
            if (q < 4) p0[q] = fmaxf(lo + hi, 0.f); else p1[q-4] = fmaxf(lo + hi, 0.f);
        }
        *(float4*)&bufT2[lane * PA + c0]     = o0;
        *(float4*)&bufT2[lane * PA + c0 + 4] = o1;
        #pragma unroll
        for (int q = 0; q < 8; q++) {
            unpack2(acc1[q], lo, hi);
            if (q < 4) p0[q] = fmaxf(lo + hi, 0.f); else p1[q-4] = fmaxf(lo + hi, 0.f);
        }
        *(float4*)&bufT2[SAMP_F + lane * PA + c0]     = o0;
        *(float4*)&bufT2[SAMP_F + lane * PA + c0 + 4] = o1;
    }
    __syncthreads();

    // ---- restage: sW <- I1W ----
    {
        const float4* W1 = (const float4*)I1W;
        #pragma unroll
        for (int q = 0; q < 4; q++)
            ((float4*)sW)[tid + q * 256] = __ldg(W1 + tid + q * 256);
    }
    __syncthreads();

    // ---- stage 3: a = h2 @ I1W^T -> fp16 rows aH[s][obj][AH] (alias of bufT1) ----
    {
        u64 acc0[8] = {0,0,0,0,0,0,0,0}, acc1[8] = {0,0,0,0,0,0,0,0};
        const float4* hvA = (const float4*)&bufT2[lane * PA];
        const float4* hvB = (const float4*)&bufT2[SAMP_F + lane * PA];
        #pragma unroll
        for (int k4 = 0; k4 < 16; k4++) {
            float4 hA = hvA[k4], hB = hvB[k4];
            u64 hA0 = pack2(hA.x, hA.y), hA1 = pack2(hA.z, hA.w);
            u64 hB0 = pack2(hB.x, hB.y), hB1 = pack2(hB.z, hB.w);
            int kb = k4 * 4;
            #pragma unroll
            for (int q = 0; q < 8; q++) {
                ulonglong2 w = *(const ulonglong2*)&sW[(c0 + q) * 64 + kb];
                acc0[q] = ffma2(hA0, w.x, acc0[q]); acc0[q] = ffma2(hA1, w.y, acc0[q]);
                acc1[q] = ffma2(hB0, w.x, acc1[q]); acc1[q] = ffma2(hB1, w.y, acc1[q]);
            }
        }
        __half* aH = (__half*)bufT1;
        float f[8]; float lo, hi;
        #pragma unroll
        for (int q = 0; q < 8; q++) { unpack2(acc0[q], lo, hi); f[q] = lo + hi; }
        {
            uint4 st;
            st.x = h2u(__floats2half2_rn(f[0], f[1]));
            st.y = h2u(__floats2half2_rn(f[2], f[3]));
            st.z = h2u(__floats2half2_rn(f[4], f[5]));
            st.w = h2u(__floats2half2_rn(f[6], f[7]));
            *(uint4*)&aH[lane * AH + c0] = st;            // 16B, conflict-free phases
        }
        #pragma unroll
        for (int q = 0; q < 8; q++) { unpack2(acc1[q], lo, hi); f[q] = lo + hi; }
        {
            uint4 st;
            st.x = h2u(__floats2half2_rn(f[0], f[1]));
            st.y = h2u(__floats2half2_rn(f[2], f[3]));
            st.z = h2u(__floats2half2_rn(f[4], f[5]));
            st.w = h2u(__floats2half2_rn(f[6], f[7]));
            *(uint4*)&aH[SAMP_H + lane * AH + c0] = st;
        }
    }
    __syncthreads();

    // ---- pair stage (R10 mapping): unit = (i, j0, j1), same unit for both samples ----
    {
        int i = 0, base = 0;
        while (tid >= base + ((32 - i) >> 1)) { base += (32 - i) >> 1; ++i; }
        const int u  = tid - base;
        const int nu = (32 - i) >> 1;
        const int j0 = i + 1 + u;
        const int j1 = j0 + nu;
        const bool has2 = (j1 <= 31);
        const int j1c = has2 ? j1 : j0;

        const __half* aH = (const __half*)bufT1;
        const uint4* Ai0  = (const uint4*)(aH + i   * AH);           // near-uniform
        const uint4* Aj00 = (const uint4*)(aH + j0  * AH);           // conflict-free
        const uint4* Aj01 = (const uint4*)(aH + j1c * AH);
        const uint4* Ai1  = (const uint4*)(aH + SAMP_H + i   * AH);
        const uint4* Aj10 = (const uint4*)(aH + SAMP_H + j0  * AH);
        const uint4* Aj11 = (const uint4*)(aH + SAMP_H + j1c * AH);

        u64 P[4][4] = {};   // [(s0,j0),(s0,j1),(s1,j0),(s1,j1)][feature-pair]
        #pragma unroll
        for (int k = 0; k < 8; k++) {                    // 8 halves per chunk
            uint4 ra0 = Ai0[k],  ra1 = Ai1[k];
            uint4 rc0 = Aj00[k], rc1 = Aj01[k];
            uint4 rd0 = Aj10[k], rd1 = Aj11[k];
            const __half2* HA0 = (const __half2*)&ra0;
            const __half2* HA1 = (const __half2*)&ra1;
            const __half2* HC0 = (const __half2*)&rc0;
            const __half2* HC1 = (const __half2*)&rc1;
            const __half2* HD0 = (const __half2*)&rd0;
            const __half2* HD1 = (const __half2*)&rd1;
            #pragma unroll
            for (int sub = 0; sub < 2; sub++) {
                float2 tA[4][2];
                {
                    __half2 a = HA0[2*sub], b = HA0[2*sub+1];
                    tA[0][0] = __half22float2(mg_h2tanh(__hsub2(a, HC0[2*sub])));
                    tA[0][1] = __half22float2(mg_h2tanh(__hsub2(b, HC0[2*sub+1])));
                    tA[1][0] = __half22float2(mg_h2tanh(__hsub2(a, HC1[2*sub])));
                    tA[1][1] = __half22float2(mg_h2tanh(__hsub2(b, HC1[2*sub+1])));
                }
                {
                    __half2 a = HA1[2*sub], b = HA1[2*sub+1];
                    tA[2][0] = __half22float2(mg_h2tanh(__hsub2(a, HD0[2*sub])));
                    tA[2][1] = __half22float2(mg_h2tanh(__hsub2(b, HD0[2*sub+1])));
                    tA[3][0] = __half22float2(mg_h2tanh(__hsub2(a, HD1[2*sub])));
                    tA[3][1] = __half22float2(mg_h2tanh(__hsub2(b, HD1[2*sub+1])));
                }
                #pragma unroll
                for (int e = 0; e < 4; e++) {
                    int h = k * 8 + sub * 4 + e;
                    const ulonglong2* wp = (const ulonglong2*)&sI2[h * 8];
                    ulonglong2 wa = wp[0], wb = wp[1];   // 1 bcast, 4 pair-instances
                    #pragma unroll
                    for (int pi = 0; pi < 4; pi++) {
                        float tv = (e & 1) ? tA[pi][e >> 1].y : tA[pi][e >> 1].x;
                        u64 tt = pack2(tv, tv);
                        P[pi][0] = ffma2(tt, wa.x, P[pi][0]);
                        P[pi][1] = ffma2(tt, wa.y, P[pi][1]);
                        P[pi][2] = ffma2(tt, wb.x, P[pi][2]);
                        P[pi][3] = ffma2(tt, wb.y, P[pi][3]);
                    }
                }
            }
        }

        const int rbi = rb(i);
        #pragma unroll
        for (int pp = 0; pp < 2; pp++) {
            if (pp == 1 && !has2) break;
            int j = pp ? j1 : j0;
            int idx_ij = i * 31 + (j - 1);
            int idx_ji = j * 31 + i;
            float4 gi0 = __ldg((const float4*)(I3 + idx_ij * 8));
            float4 gi1 = __ldg((const float4*)(I3 + idx_ij * 8) + 1);
            float4 gj0 = __ldg((const float4*)(I3 + idx_ji * 8));
            float4 gj1 = __ldg((const float4*)(I3 + idx_ji * 8) + 1);
            int p = rbi + (j - i - 1);
            #pragma unroll
            for (int s2 = 0; s2 < 2; s2++) {             // I3 loaded once, both samples
                int pi = s2 * 2 + pp;
                float t[8];
                unpack2(P[pi][0], t[0], t[1]); unpack2(P[pi][1], t[2], t[3]);
                unpack2(P[pi][2], t[4], t[5]); unpack2(P[pi][3], t[6], t[7]);
                #pragma unroll
                for (int f = 0; f < 8; f++) t[f] = tanh_fast(t[f]);
                float4 res;
                res.x = t[0]*gi0.x + t[1]*gi0.y + t[2]*gi0.z + t[3]*gi0.w;
                res.y = t[4]*gi1.x + t[5]*gi1.y + t[6]*gi1.z + t[7]*gi1.w;
                res.z = -(t[0]*gj0.x + t[1]*gj0.y + t[2]*gj0.z + t[3]*gj0.w);
                res.w = -(t[4]*gj1.x + t[5]*gj1.y + t[6]*gj1.z + t[7]*gj1.w);
                ((float4*)(sPair + s2 * NPAIR * 4))[p] = res;   // bufT2 region (dead)
            }
        }
    }
    __syncthreads();

    // ---- parallel deterministic reduction: 4 threads per (sample, object) ----
    {
        const int s2 = tid >> 7;          // sample
        const int o  = (tid >> 2) & 31;   // object
        const int q  = tid & 3;           // quarter
        const float2* sp2 = (const float2*)(sPair + s2 * NPAIR * 4);
        float a0 = 0.f, a1 = 0.f;
        const int nrow = 31 - o;          // row terms (j > o), then col terms
        for (int mm = q; mm < 31; mm += 4) {
            int p, half;
            if (mm < nrow) { p = rb(o) + mm; half = 0; }
            else           { int k = mm - nrow; p = rb(k) + (o - k - 1); half = 1; }
            float2 v = sp2[p * 2 + half];
            a0 += v.x; a1 += v.y;
        }
        a0 += __shfl_xor_sync(0xffffffffu, a0, 1);
        a1 += __shfl_xor_sync(0xffffffffu, a1, 1);
        a0 += __shfl_xor_sync(0xffffffffu, a0, 2);
        a1 += __shfl_xor_sync(0xffffffffu, a1, 2);
        if (q == 0) {
            float2 r;
            r.x = a0 + sRes[(s2 * N_OBJ + o) * 2 + 0];
            r.y = a1 + sRes[(s2 * N_OBJ + o) * 2 + 1];
            ((float2*)out)[(bid * 2 + s2) * N_OBJ + o] = r;
        }
    }
}

extern "C" void kernel_launch(void* const* d_in, const int* in_sizes, int n_in,
                              void* d_out, int out_size) {
    const float* inputs = (const float*)d_in[0];
    const float* L1W    = (const float*)d_in[1];
    const float* L1b    = (const float*)d_in[2];
    const float* L2W    = (const float*)d_in[3];
    const float* L2b    = (const float*)d_in[4];
    const float* I1W    = (const float*)d_in[5];
    const float* I2W    = (const float*)d_in[6];
    const float* I3     = (const float*)d_in[7];
    const float* S1W    = (const float*)d_in[8];
    const float* S1b    = (const float*)d_in[9];
    const float* S2W    = (const float*)d_in[10];
    const float* S2b    = (const float*)d_in[11];
    float* out = (float*)d_out;

    magnet_main<<<S_TOT / 2, 256>>>(inputs, L1W, L1b, L2W, L2b,
                                    I1W, I2W, I3, S1W, S1b, S2W, S2b, out);
}

// round 17
// speedup vs baseline: 1.0587x; 1.0587x over previous
#include <cuda_runtime.h>

#define S_TOT   4096
#define N_OBJ   32
#define H_D     64
#define PA      68                 // row stride in floats; conflict-free LDS.128
#define NPAIR   496
#define SAMP_F  (N_OBJ * PA)       // 2176 floats per sample region
#define NBLK    456                // 3 blocks x 152 SMs, persistent
#define NITEMS  (S_TOT / 2)        // 2048 sample-pairs

typedef unsigned long long u64;

__device__ __forceinline__ u64 pack2(float lo, float hi) {
    u64 r; asm("mov.b64 %0, {%1, %2};" : "=l"(r) : "f"(lo), "f"(hi)); return r;
}
__device__ __forceinline__ void unpack2(u64 v, float& lo, float& hi) {
    asm("mov.b64 {%0, %1}, %2;" : "=f"(lo), "=f"(hi) : "l"(v));
}
__device__ __forceinline__ u64 ffma2(u64 a, u64 b, u64 c) {
    u64 d; asm("fma.rn.f32x2 %0, %1, %2, %3;" : "=l"(d) : "l"(a), "l"(b), "l"(c)); return d;
}
__device__ __forceinline__ float tanh_fast(float x) {   // 1 MUFU
    float y; asm("tanh.approx.f32 %0, %1;" : "=f"(y) : "f"(x)); return y;
}
__device__ __forceinline__ int rb(int x) { return x * 31 - ((x * (x - 1)) >> 1); }

__global__ __launch_bounds__(256, 3)
void magnet_main(const float* __restrict__ X,     // [S,32,4]
                 const float* __restrict__ L1W,   // [64,4]
                 const float* __restrict__ L1b,   // [64]
                 const float* __restrict__ L2W,   // [64,64]
                 const float* __restrict__ L2b,   // [64]
                 const float* __restrict__ I1W,   // [64,64]
                 const float* __restrict__ I2W,   // [8,64]
                 const float* __restrict__ I3,    // [992,2,4]
                 const float* __restrict__ S1W,   // [4,4]
                 const float* __restrict__ S1b,   // [4]
                 const float* __restrict__ S2W,   // [32,2,2]
                 const float* __restrict__ S2b,   // [32,2]
                 float* __restrict__ out)         // [S,32,2]
{
    // 2 samples per iteration; activations row-major f32 [s][obj][PA]
    __shared__ __align__(16) float bufT1[2 * SAMP_F];       // h1; reused as a
    __shared__ __align__(16) float bufT2_sPair[2 * SAMP_F]; // h2; alias sPair [s][496][4]
    __shared__ __align__(16) float sWL2[H_D * H_D];         // L2W row-major [c][k]
    __shared__ __align__(16) float sWI1[H_D * H_D];         // I1W row-major [c][k]
    __shared__ __align__(16) float sI2[H_D * 8];            // [h][f]
    __shared__ __align__(16) float sX[2 * N_OBJ * 4];
    __shared__ __align__(16) float sL1W[H_D * 4];
    __shared__ float sL1b[H_D];
    __shared__ float sL2b[H_D];
    __shared__ float sRes[2 * N_OBJ * 2];

    float* bufT2 = bufT2_sPair;
    float* sPair = bufT2_sPair;

    const int tid  = threadIdx.x;
    const int wS   = tid >> 5;       // warp 0..7
    const int lane = tid & 31;       // = object in encoder stages
    const int c0   = wS * 8;         // 8 channels per warp (warp-uniform)

    // ---- one-time staging: all weights ----
    {
        const float4* W2 = (const float4*)L2W;
        const float4* W1 = (const float4*)I1W;
        #pragma unroll
        for (int q = 0; q < 4; q++) {
            ((float4*)sWL2)[tid + q * 256] = __ldg(W2 + tid + q * 256);
            ((float4*)sWI1)[tid + q * 256] = __ldg(W1 + tid + q * 256);
        }
        #pragma unroll
        for (int e = 0; e < 2; e++) {                 // sI2[h][f] = I2W[f][h]
            int idx = tid + e * 256;
            int h = idx >> 3, f = idx & 7;
            sI2[idx] = __ldg(I2W + f * 64 + h);
        }
        if (tid < 64)        ((float4*)sL1W)[tid] = __ldg(((const float4*)L1W) + tid);
        else if (tid < 128)  sL1b[tid - 64]  = __ldg(L1b + tid - 64);
        else if (tid < 192)  sL2b[tid - 128] = __ldg(L2b + tid - 128);
    }
    __syncthreads();

    // ---- persistent loop over sample-pairs ----
    for (int it = blockIdx.x; it < NITEMS; it += NBLK) {

        // per-iteration input staging
        if (tid < 64)
            ((float4*)sX)[tid] = __ldg(((const float4*)X) + it * 64 + tid);
        __syncthreads();

        // ---- stage 1: h1 = relu(x @ L1W^T + L1b), row-major float4 writes ----
        {
            float4 x0 = ((const float4*)sX)[lane];
            float4 x1 = ((const float4*)sX)[N_OBJ + lane];
            float4 oA0, oA1, oB0, oB1;
            float* pA0 = (float*)&oA0; float* pA1 = (float*)&oA1;
            float* pB0 = (float*)&oB0; float* pB1 = (float*)&oB1;
            #pragma unroll
            for (int q = 0; q < 8; q++) {
                int c = c0 + q;
                float4 w = ((const float4*)sL1W)[c];         // broadcast (both samples)
                float b = sL1b[c];
                float v0 = fmaf(x0.x, w.x, fmaf(x0.y, w.y, fmaf(x0.z, w.z, fmaf(x0.w, w.w, b))));
                float v1 = fmaf(x1.x, w.x, fmaf(x1.y, w.y, fmaf(x1.z, w.z, fmaf(x1.w, w.w, b))));
                if (q < 4) { pA0[q]   = fmaxf(v0, 0.f); pB0[q]   = fmaxf(v1, 0.f); }
                else       { pA1[q-4] = fmaxf(v0, 0.f); pB1[q-4] = fmaxf(v1, 0.f); }
            }
            *(float4*)&bufT1[lane * PA + c0]              = oA0;
            *(float4*)&bufT1[lane * PA + c0 + 4]          = oA1;
            *(float4*)&bufT1[SAMP_F + lane * PA + c0]     = oB0;
            *(float4*)&bufT1[SAMP_F + lane * PA + c0 + 4] = oB1;
        }
        // ---- self term (64 threads = 2 samples x 32 obj) -> sRes ----
        if (tid < 64) {
            int o = tid & 31;
            float4 xv = ((const float4*)sX)[tid];
            float hs[4];
            #pragma unroll
            for (int f = 0; f < 4; f++) {
                float4 w = __ldg(((const float4*)S1W) + f);
                hs[f] = fmaxf(xv.x*w.x + xv.y*w.y + xv.z*w.z + xv.w*w.w + __ldg(S1b + f), 0.f);
            }
            float4 s2 = __ldg(((const float4*)S2W) + o);
            sRes[tid * 2 + 0] = hs[0] * s2.x + hs[1] * s2.y + __ldg(S2b + o * 2 + 0);
            sRes[tid * 2 + 1] = hs[2] * s2.z + hs[3] * s2.w + __ldg(S2b + o * 2 + 1);
        }
        __syncthreads();

        // ---- stage 2: h2 = relu(h1 @ L2W^T + L2b) -> bufT2 row-major ----
        {
            u64 acc0[8], acc1[8];
            #pragma unroll
            for (int q = 0; q < 8; q++) { acc0[q] = pack2(sL2b[c0 + q], 0.f); acc1[q] = acc0[q]; }
            const float4* hvA = (const float4*)&bufT1[lane * PA];
            const float4* hvB = (const float4*)&bufT1[SAMP_F + lane * PA];
            #pragma unroll
            for (int k4 = 0; k4 < 16; k4++) {
                float4 hA = hvA[k4], hB = hvB[k4];           // conflict-free LDS.128
                u64 hA0 = pack2(hA.x, hA.y), hA1 = pack2(hA.z, hA.w);
                u64 hB0 = pack2(hB.x, hB.y), hB1 = pack2(hB.z, hB.w);
                int kb = k4 * 4;
                #pragma unroll
                for (int q = 0; q < 8; q++) {
                    ulonglong2 w = *(const ulonglong2*)&sWL2[(c0 + q) * 64 + kb]; // bcast
                    acc0[q] = ffma2(hA0, w.x, acc0[q]); acc0[q] = ffma2(hA1, w.y, acc0[q]);
                    acc1[q] = ffma2(hB0, w.x, acc1[q]); acc1[q] = ffma2(hB1, w.y, acc1[q]);
                }
            }
            float4 o0, o1; float lo, hi;
            float* p0 = (float*)&o0; float* p1 = (float*)&o1;
            #pragma unroll
            for (int q = 0; q < 8; q++) {
                unpack2(acc0[q], lo, hi);
                if (q < 4) p0[q] = fmaxf(lo + hi, 0.f); else p1[q-4] = fmaxf(lo + hi, 0.f);
            }
            *(float4*)&bufT2[lane * PA + c0]     = o0;
            *(float4*)&bufT2[lane * PA + c0 + 4] = o1;
            #pragma unroll
            for (int q = 0; q < 8; q++) {
                unpack2(acc1[q], lo, hi);
                if (q < 4) p0[q] = fmaxf(lo + hi, 0.f); else p1[q-4] = fmaxf(lo + hi, 0.f);
            }
            *(float4*)&bufT2[SAMP_F + lane * PA + c0]     = o0;
            *(float4*)&bufT2[SAMP_F + lane * PA + c0 + 4] = o1;
        }
        __syncthreads();

        // ---- stage 3: a = h2 @ I1W^T -> bufT1 row-major (no restage needed) ----
        {
            u64 acc0[8] = {0,0,0,0,0,0,0,0}, acc1[8] = {0,0,0,0,0,0,0,0};
            const float4* hvA = (const float4*)&bufT2[lane * PA];
            const float4* hvB = (const float4*)&bufT2[SAMP_F + lane * PA];
            #pragma unroll
            for (int k4 = 0; k4 < 16; k4++) {
                float4 hA = hvA[k4], hB = hvB[k4];
                u64 hA0 = pack2(hA.x, hA.y), hA1 = pack2(hA.z, hA.w);
                u64 hB0 = pack2(hB.x, hB.y), hB1 = pack2(hB.z, hB.w);
                int kb = k4 * 4;
                #pragma unroll
                for (int q = 0; q < 8; q++) {
                    ulonglong2 w = *(const ulonglong2*)&sWI1[(c0 + q) * 64 + kb];
                    acc0[q] = ffma2(hA0, w.x, acc0[q]); acc0[q] = ffma2(hA1, w.y, acc0[q]);
                    acc1[q] = ffma2(hB0, w.x, acc1[q]); acc1[q] = ffma2(hB1, w.y, acc1[q]);
                }
            }
            float4 o0, o1; float lo, hi;
            float* p0 = (float*)&o0; float* p1 = (float*)&o1;
            #pragma unroll
            for (int q = 0; q < 8; q++) {
                unpack2(acc0[q], lo, hi);
                if (q < 4) p0[q] = lo + hi; else p1[q-4] = lo + hi;
            }
            *(float4*)&bufT1[lane * PA + c0]     = o0;
            *(float4*)&bufT1[lane * PA + c0 + 4] = o1;
            #pragma unroll
            for (int q = 0; q < 8; q++) {
                unpack2(acc1[q], lo, hi);
                if (q < 4) p0[q] = lo + hi; else p1[q-4] = lo + hi;
            }
            *(float4*)&bufT1[SAMP_F + lane * PA + c0]     = o0;
            *(float4*)&bufT1[SAMP_F + lane * PA + c0 + 4] = o1;
        }
        __syncthreads();

        // ---- pair stage (R10 mapping): unit = (i, j0, j1), same unit both samples ----
        {
            int i = 0, base = 0;
            while (tid >= base + ((32 - i) >> 1)) { base += (32 - i) >> 1; ++i; }
            const int u  = tid - base;
            const int nu = (32 - i) >> 1;
            const int j0 = i + 1 + u;
            const int j1 = j0 + nu;
            const bool has2 = (j1 <= 31);
            const int j1c = has2 ? j1 : j0;

            const float4* A = (const float4*)bufT1;      // rows of 17 float4; s1 at +544
            const float4* ai0  = A + i * 17;
            const float4* aj00 = A + j0 * 17;
            const float4* aj01 = A + j1c * 17;
            const float4* ai1  = A + 544 + i * 17;
            const float4* aj10 = A + 544 + j0 * 17;
            const float4* aj11 = A + 544 + j1c * 17;

            u64 P[4][4] = {};   // [s0p0, s0p1, s1p0, s1p1][feature-pair]
            #pragma unroll
            for (int k4 = 0; k4 < 16; k4++) {
                float4 x0 = ai0[k4], y00 = aj00[k4], y01 = aj01[k4];
                float4 x1 = ai1[k4], y10 = aj10[k4], y11 = aj11[k4];
                const float* fx0 = (const float*)&x0;
                const float* f00 = (const float*)&y00;
                const float* f01 = (const float*)&y01;
                const float* fx1 = (const float*)&x1;
                const float* f10 = (const float*)&y10;
                const float* f11 = (const float*)&y11;
                #pragma unroll
                for (int v = 0; v < 4; v++) {
                    float t0 = tanh_fast(fx0[v] - f00[v]);
                    float t1 = tanh_fast(fx0[v] - f01[v]);
                    float t2 = tanh_fast(fx1[v] - f10[v]);
                    float t3 = tanh_fast(fx1[v] - f11[v]);
                    const ulonglong2* wp = (const ulonglong2*)&sI2[(k4 * 4 + v) * 8];
                    ulonglong2 wa = wp[0], wb = wp[1];   // 1 bcast, 4 pair-instances
                    u64 tt;
                    tt = pack2(t0, t0);
                    P[0][0] = ffma2(tt, wa.x, P[0][0]); P[0][1] = ffma2(tt, wa.y, P[0][1]);
                    P[0][2] = ffma2(tt, wb.x, P[0][2]); P[0][3] = ffma2(tt, wb.y, P[0][3]);
                    tt = pack2(t1, t1);
                    P[1][0] = ffma2(tt, wa.x, P[1][0]); P[1][1] = ffma2(tt, wa.y, P[1][1]);
                    P[1][2] = ffma2(tt, wb.x, P[1][2]); P[1][3] = ffma2(tt, wb.y, P[1][3]);
                    tt = pack2(t2, t2);
                    P[2][0] = ffma2(tt, wa.x, P[2][0]); P[2][1] = ffma2(tt, wa.y, P[2][1]);
                    P[2][2] = ffma2(tt, wb.x, P[2][2]); P[2][3] = ffma2(tt, wb.y, P[2][3]);
                    tt = pack2(t3, t3);
                    P[3][0] = ffma2(tt, wa.x, P[3][0]); P[3][1] = ffma2(tt, wa.y, P[3][1]);
                    P[3][2] = ffma2(tt, wb.x, P[3][2]); P[3][3] = ffma2(tt, wb.y, P[3][3]);
                }
            }

            const int rbi = rb(i);
            #pragma unroll
            for (int pp = 0; pp < 2; pp++) {
                if (pp == 1 && !has2) break;
                int j = pp ? j1 : j0;
                int idx_ij = i * 31 + (j - 1);
                int idx_ji = j * 31 + i;
                float4 gi0 = __ldg((const float4*)(I3 + idx_ij * 8));
                float4 gi1 = __ldg((const float4*)(I3 + idx_ij * 8) + 1);
                float4 gj0 = __ldg((const float4*)(I3 + idx_ji * 8));
                float4 gj1 = __ldg((const float4*)(I3 + idx_ji * 8) + 1);
                int p = rbi + (j - i - 1);
                #pragma unroll
                for (int s2 = 0; s2 < 2; s2++) {         // I3 loaded once, both samples
                    int pi = s2 * 2 + pp;
                    float t[8];
                    unpack2(P[pi][0], t[0], t[1]); unpack2(P[pi][1], t[2], t[3]);
                    unpack2(P[pi][2], t[4], t[5]); unpack2(P[pi][3], t[6], t[7]);
                    #pragma unroll
                    for (int f = 0; f < 8; f++) t[f] = tanh_fast(t[f]);
                    float4 res;
                    res.x = t[0]*gi0.x + t[1]*gi0.y + t[2]*gi0.z + t[3]*gi0.w;
                    res.y = t[4]*gi1.x + t[5]*gi1.y + t[6]*gi1.z + t[7]*gi1.w;
                    res.z = -(t[0]*gj0.x + t[1]*gj0.y + t[2]*gj0.z + t[3]*gj0.w);
                    res.w = -(t[4]*gj1.x + t[5]*gj1.y + t[6]*gj1.z + t[7]*gj1.w);
                    ((float4*)(sPair + s2 * NPAIR * 4))[p] = res;   // bufT2 region (dead)
                }
            }
        }
        __syncthreads();

        // ---- parallel deterministic reduction: 4 threads per (sample, object) ----
        {
            const int s2 = tid >> 7;          // sample
            const int o  = (tid >> 2) & 31;   // object
            const int q  = tid & 3;           // quarter
            const float2* sp2 = (const float2*)(sPair + s2 * NPAIR * 4);
            float a0 = 0.f, a1 = 0.f;
            const int nrow = 31 - o;          // row terms (j > o), then col terms
            for (int mm = q; mm < 31; mm += 4) {
                int p, half;
                if (mm < nrow) { p = rb(o) + mm; half = 0; }
                else           { int k = mm - nrow; p = rb(k) + (o - k - 1); half = 1; }
                float2 v = sp2[p * 2 + half];
                a0 += v.x; a1 += v.y;
            }
            a0 += __shfl_xor_sync(0xffffffffu, a0, 1);
            a1 += __shfl_xor_sync(0xffffffffu, a1, 1);
            a0 += __shfl_xor_sync(0xffffffffu, a0, 2);
            a1 += __shfl_xor_sync(0xffffffffu, a1, 2);
            if (q == 0) {
                float2 r;
                r.x = a0 + sRes[(s2 * N_OBJ + o) * 2 + 0];
                r.y = a1 + sRes[(s2 * N_OBJ + o) * 2 + 1];
                ((float2*)out)[(it * 2 + s2) * N_OBJ + o] = r;
            }
        }
        __syncthreads();   // protect sX/bufT1/sPair reuse next iteration
    }
}

extern "C" void kernel_launch(void* const* d_in, const int* in_sizes, int n_in,
                              void* d_out, int out_size) {
    const float* inputs = (const float*)d_in[0];
    const float* L1W    = (const float*)d_in[1];
    const float* L1b    = (const float*)d_in[2];
    const float* L2W    = (const float*)d_in[3];
    const float* L2b    = (const float*)d_in[4];
    const float* I1W    = (const float*)d_in[5];
    const float* I2W    = (const float*)d_in[6];
    const float* I3     = (const float*)d_in[7];
    const float* S1W    = (const float*)d_in[8];
    const float* S1b    = (const float*)d_in[9];
    const float* S2W    = (const float*)d_in[10];
    const float* S2b    = (const float*)d_in[11];
    float* out = (float*)d_out;

    magnet_main<<<NBLK, 256>>>(inputs, L1W, L1b, L2W, L2b,
                               I1W, I2W, I3, S1W, S1b, S2W, S2b, out);
}